// round 13
// baseline (speedup 1.0000x reference)
#include <cuda_runtime.h>
#include <cstdint>

#define HG_L 16
#define HG_T (1u << 19)
#define HG_TMASK (HG_T - 1u)
#define WIDTH 64

#define P1 2654435761u
#define P2 805459861u
#define P3 3674653429u

typedef unsigned long long u64;

// Feature scratch: 48 level-slices x 2^20 points, one packed f32x2 each.
#define NPAD_LOG2 20
__device__ u64 g_enc[48u << NPAD_LOG2];   // 402 MB static scratch

// floor(16 * 1.5^l) for l = 0..15
__constant__ float c_res[HG_L] = {
    16.f, 24.f, 36.f, 54.f, 81.f, 121.f, 182.f, 273.f,
    410.f, 615.f, 922.f, 1383.f, 2075.f, 3113.f, 4670.f, 7006.f
};

// ---------- packed f32x2 helpers (Blackwell FFMA2) ----------
__device__ __forceinline__ u64 ffma2(u64 a, u64 b, u64 c) {
    u64 d;
    asm("fma.rn.f32x2 %0, %1, %2, %3;" : "=l"(d) : "l"(a), "l"(b), "l"(c));
    return d;
}
__device__ __forceinline__ u64 dup2(float x) {
    u64 d;
    asm("mov.b64 %0, {%1, %1};" : "=l"(d) : "f"(x));
    return d;
}
__device__ __forceinline__ u64 pack2(float lo, float hi) {
    u64 d;
    asm("mov.b64 %0, {%1, %2};" : "=l"(d) : "f"(lo), "f"(hi));
    return d;
}
__device__ __forceinline__ void unpack2(u64 x, float& lo, float& hi) {
    asm("mov.b64 {%0, %1}, %2;" : "=f"(lo), "=f"(hi) : "l"(x));
}
__device__ __forceinline__ u64 relu2(u64 x) {
    float lo, hi;
    unpack2(x, lo, hi);
    return pack2(fmaxf(lo, 0.f), fmaxf(hi, 0.f));
}

// ---------- gather primitive (R3 scheme, measured best) ----------
__device__ __forceinline__ void gather_pair(const float2* __restrict__ base,
                                            bool even, uint32_t ax0, uint32_t e,
                                            float vx0, float vx1, float wt,
                                            float& f0, float& f1) {
    if (even) {
        uint32_t id0 = (ax0 ^ e) & HG_TMASK;
        float4 q = __ldg((const float4*)base + (id0 >> 1));
        bool h = (id0 & 1u) != 0u;
        float wl = h ? vx1 : vx0;
        float wh = h ? vx0 : vx1;
        f0 = fmaf(wt, fmaf(wl, q.x, wh * q.z), f0);
        f1 = fmaf(wt, fmaf(wl, q.y, wh * q.w), f1);
    } else {
        float2 u = __ldg(base + ((ax0 ^ e) & HG_TMASK));
        float2 v = __ldg(base + (((ax0 + 1u) ^ e) & HG_TMASK));
        f0 = fmaf(wt, fmaf(vx0, u.x, vx1 * v.x), f0);
        f1 = fmaf(wt, fmaf(vx0, u.y, vx1 * v.y), f1);
    }
}

__device__ __forceinline__ void level3(float x0, float x1, float x2, float r,
                                       const float2* __restrict__ base,
                                       float& f0, float& f1) {
    float px = x0 * r, py = x1 * r, pz = x2 * r;
    float fx = floorf(px), fy = floorf(py), fz = floorf(pz);
    float wx = px - fx, wy = py - fy, wz = pz - fz;

    uint32_t ax0 = (uint32_t)fx;
    uint32_t ey0 = (uint32_t)fy * P1, ey1 = ey0 + P1;
    uint32_t ez0 = (uint32_t)fz * P2, ez1 = ez0 + P2;
    float vx0 = 1.f - wx, vx1 = wx;
    float vy0 = 1.f - wy, vy1 = wy;
    float vz0 = 1.f - wz, vz1 = wz;
    const bool even = (ax0 & 1u) == 0u;

    f0 = 0.f; f1 = 0.f;
    gather_pair(base, even, ax0, ey0 ^ ez0, vx0, vx1, vy0 * vz0, f0, f1);
    gather_pair(base, even, ax0, ey0 ^ ez1, vx0, vx1, vy0 * vz1, f0, f1);
    gather_pair(base, even, ax0, ey1 ^ ez0, vx0, vx1, vy1 * vz0, f0, f1);
    gather_pair(base, even, ax0, ey1 ^ ez1, vx0, vx1, vy1 * vz1, f0, f1);
}

__device__ __forceinline__ void level4(float x0, float x1, float x2, float x3,
                                       float r, const float2* __restrict__ base,
                                       float& f0, float& f1) {
    float px = x0 * r, py = x1 * r, pz = x2 * r, pw = x3 * r;
    float fx = floorf(px), fy = floorf(py), fz = floorf(pz), fw = floorf(pw);
    float wx = px - fx, wy = py - fy, wz = pz - fz, ww = pw - fw;

    uint32_t ax0 = (uint32_t)fx;
    uint32_t ey[2], ez[2], ew[2];
    ey[0] = (uint32_t)fy * P1;  ey[1] = ey[0] + P1;
    ez[0] = (uint32_t)fz * P2;  ez[1] = ez[0] + P2;
    ew[0] = (uint32_t)fw * P3;  ew[1] = ew[0] + P3;
    float vx0 = 1.f - wx, vx1 = wx;
    float vy[2] = {1.f - wy, wy};
    float vz[2] = {1.f - wz, wz};
    float vw[2] = {1.f - ww, ww};
    const bool even = (ax0 & 1u) == 0u;

    f0 = 0.f; f1 = 0.f;
#pragma unroll
    for (int c = 0; c < 8; c++) {
        const int by = (c >> 2) & 1, bz = (c >> 1) & 1, bw = c & 1;
        gather_pair(base, even, ax0, ey[by] ^ ez[bz] ^ ew[bw],
                    vx0, vx1, vy[by] * (vz[bz] * vw[bw]), f0, f1);
    }
}

// ---------- kernel 1: encode only (R9 form, measured best) ----------
__global__ __launch_bounds__(256)
void encode_kernel(const float* __restrict__ fc,
                   const float* __restrict__ fn,
                   const float* __restrict__ pe,
                   const float* __restrict__ pos_tab,
                   const float* __restrict__ nrm_tab,
                   const float* __restrict__ pose_tab,
                   int n) {
    const int idx = blockIdx.x * 256 + threadIdx.x;
    if (idx >= n) return;

    {
        float x0 = __ldg(fc + (size_t)idx * 3 + 0);
        float x1 = __ldg(fc + (size_t)idx * 3 + 1);
        float x2 = __ldg(fc + (size_t)idx * 3 + 2);
#pragma unroll 1
        for (int l = 0; l < HG_L; l++) {
            const float2* base = (const float2*)pos_tab + (size_t)l * HG_T;
            float f0, f1;
            level3(x0, x1, x2, c_res[l], base, f0, f1);
            g_enc[((size_t)l << NPAD_LOG2) + idx] = pack2(f0, f1);
        }
    }
    {
        float x0 = __ldg(fn + (size_t)idx * 3 + 0);
        float x1 = __ldg(fn + (size_t)idx * 3 + 1);
        float x2 = __ldg(fn + (size_t)idx * 3 + 2);
#pragma unroll 1
        for (int l = 0; l < HG_L; l++) {
            const float2* base = (const float2*)nrm_tab + (size_t)l * HG_T;
            float f0, f1;
            level3(x0, x1, x2, c_res[l], base, f0, f1);
            g_enc[((size_t)(16 + l) << NPAD_LOG2) + idx] = pack2(f0, f1);
        }
    }
    {
        float x0 = __ldg(pe + (size_t)idx * 4 + 0);
        float x1 = __ldg(pe + (size_t)idx * 4 + 1);
        float x2 = __ldg(pe + (size_t)idx * 4 + 2);
        float x3 = __ldg(pe + (size_t)idx * 4 + 3);
#pragma unroll 1
        for (int l = 0; l < HG_L; l++) {
            const float2* base = (const float2*)pose_tab + (size_t)l * HG_T;
            float f0, f1;
            level4(x0, x1, x2, x3, c_res[l], base, f0, f1);
            g_enc[((size_t)(32 + l) << NPAD_LOG2) + idx] = pack2(f0, f1);
        }
    }
}

// ---------- kernel 2: warp-cooperative MLP ----------
// Block = 256 threads = 2 teams x 4 warps. Each warp owns 16 neurons; lanes
// are points (2 groups of 32 -> 64 points per team-pass). Each weight read
// (broadcast LDS.128) feeds 64 points. 4 passes -> 512 points per block.
// h1 crosses warps via smem; layer 3 fused into layer 2 + 4-warp reduce.

#define MLP_SMEM_BYTES 95488
// layout (bytes):
//   [0,      24576)  W1s  [96][64] float
//   [24576,  40960)  W2s  [64][64] float (natural)
//   [40960,  43264)  W3s  [64][9]  float
//   [43264,  77056)  h1s  [2 teams][64 pts][33 u64] (33 = 32 pairs + pad)
//   [77056,  95488)  part [2 teams][4 warps][64 pts][9] float

__global__ __launch_bounds__(256, 2)
void mlp_kernel(const float* __restrict__ W1,
                const float* __restrict__ W2,
                const float* __restrict__ W3,
                float* __restrict__ out, int n) {
    extern __shared__ char smem_raw[];
    float* W1s = (float*)smem_raw;
    float* W2s = W1s + 96 * 64;
    float* W3s = W2s + 64 * 64;
    u64* h1s = (u64*)(smem_raw + 43264);
    float* part = (float*)(smem_raw + 77056);

    const int tid = threadIdx.x;
    for (int i = tid; i < 96 * 64; i += 256) W1s[i] = W1[i];
    for (int i = tid; i < 64 * 64; i += 256) W2s[i] = W2[i];
    for (int i = tid; i < 64 * 9; i += 256) W3s[i] = W3[i];
    __syncthreads();

    const int warp = tid >> 5, lane = tid & 31;
    const int team = warp >> 2, w4 = warp & 3;
    u64* h1t = h1s + team * (64 * 33);
    float* partt = part + team * (4 * 64 * 9);

#pragma unroll 1
    for (int pass = 0; pass < 4; pass++) {
        const int pb = blockIdx.x * 512 + team * 256 + pass * 64;
        const bool act = (pb < n);
        const int c0 = act ? min(pb + lane, n - 1) : 0;
        const int c1 = act ? min(pb + 32 + lane, n - 1) : 0;

        // ---- layer 1: 16 neurons (8 pairs) x 2 point-groups ----
        if (act) {
            u64 acc[16];
#pragma unroll
            for (int i = 0; i < 16; i++) acc[i] = 0ull;

#pragma unroll 1
            for (int l = 0; l < 48; l++) {
                u64 e0 = g_enc[((size_t)l << NPAD_LOG2) + c0];
                u64 e1 = g_enc[((size_t)l << NPAD_LOG2) + c1];
                float f00, f01, f10, f11;
                unpack2(e0, f00, f01);
                unpack2(e1, f10, f11);
                u64 F00 = dup2(f00), F01 = dup2(f01);
                u64 F10 = dup2(f10), F11 = dup2(f11);
                const ulonglong2* r0 = (const ulonglong2*)(W1s + (2 * l) * 64 + 16 * w4);
                const ulonglong2* r1 = (const ulonglong2*)(W1s + (2 * l + 1) * 64 + 16 * w4);
#pragma unroll
                for (int q = 0; q < 4; q++) {
                    ulonglong2 a = r0[q];
                    ulonglong2 b = r1[q];
                    acc[2 * q + 0] = ffma2(F00, a.x, ffma2(F01, b.x, acc[2 * q + 0]));
                    acc[2 * q + 1] = ffma2(F00, a.y, ffma2(F01, b.y, acc[2 * q + 1]));
                    acc[8 + 2 * q + 0] = ffma2(F10, a.x, ffma2(F11, b.x, acc[8 + 2 * q + 0]));
                    acc[8 + 2 * q + 1] = ffma2(F10, a.y, ffma2(F11, b.y, acc[8 + 2 * q + 1]));
                }
            }
            // relu + store this warp's neuron pairs for both point groups
#pragma unroll
            for (int q = 0; q < 8; q++) {
                h1t[(size_t)lane * 33 + 8 * w4 + q] = relu2(acc[q]);
                h1t[(size_t)(32 + lane) * 33 + 8 * w4 + q] = relu2(acc[8 + q]);
            }
        }
        __syncthreads();

        // ---- layer 2 (+ fused layer-3 partials) ----
        if (act) {
            u64 a2[16];
#pragma unroll
            for (int i = 0; i < 16; i++) a2[i] = 0ull;

            const float* h0 = (const float*)h1t + (size_t)lane * 66;
            const float* h1p = (const float*)h1t + (size_t)(32 + lane) * 66;
#pragma unroll 1
            for (int k = 0; k < 64; k++) {
                u64 H0 = dup2(h0[k]);
                u64 H1 = dup2(h1p[k]);
                const ulonglong2* wr = (const ulonglong2*)(W2s + k * 64 + 16 * w4);
#pragma unroll
                for (int q = 0; q < 4; q++) {
                    ulonglong2 a = wr[q];
                    a2[2 * q + 0] = ffma2(H0, a.x, a2[2 * q + 0]);
                    a2[2 * q + 1] = ffma2(H0, a.y, a2[2 * q + 1]);
                    a2[8 + 2 * q + 0] = ffma2(H1, a.x, a2[8 + 2 * q + 0]);
                    a2[8 + 2 * q + 1] = ffma2(H1, a.y, a2[8 + 2 * q + 1]);
                }
            }

            float po0[9], po1[9];
#pragma unroll
            for (int o = 0; o < 9; o++) { po0[o] = 0.f; po1[o] = 0.f; }
#pragma unroll
            for (int q = 0; q < 8; q++) {
                float l0, h0v, l1, h1v;
                unpack2(a2[q], l0, h0v);
                unpack2(a2[8 + q], l1, h1v);
                l0 = fmaxf(l0, 0.f); h0v = fmaxf(h0v, 0.f);
                l1 = fmaxf(l1, 0.f); h1v = fmaxf(h1v, 0.f);
                const float* wa = W3s + (16 * w4 + 2 * q) * 9;
                const float* wb = wa + 9;
#pragma unroll
                for (int o = 0; o < 9; o++) {
                    po0[o] = fmaf(l0, wa[o], fmaf(h0v, wb[o], po0[o]));
                    po1[o] = fmaf(l1, wa[o], fmaf(h1v, wb[o], po1[o]));
                }
            }
#pragma unroll
            for (int o = 0; o < 9; o++) {
                partt[((size_t)w4 * 64 + lane) * 9 + o] = po0[o];
                partt[((size_t)w4 * 64 + 32 + lane) * 9 + o] = po1[o];
            }
        }
        __syncthreads();

        // ---- reduce 4 warp-partials -> out (128 team threads, 576 values) ----
        if (act) {
            const int ttid = tid & 127;
#pragma unroll 1
            for (int s = ttid; s < 64 * 9; s += 128) {
                int pl = s / 9, o = s - pl * 9;
                int gp = pb + pl;
                if (gp < n) {
                    float v = partt[(size_t)(0 * 64 + pl) * 9 + o]
                            + partt[(size_t)(1 * 64 + pl) * 9 + o]
                            + partt[(size_t)(2 * 64 + pl) * 9 + o]
                            + partt[(size_t)(3 * 64 + pl) * 9 + o];
                    out[(size_t)gp * 9 + o] = v;
                }
            }
        }
        __syncthreads();
    }
}

extern "C" void kernel_launch(void* const* d_in, const int* in_sizes, int n_in,
                              void* d_out, int out_size) {
    const float* fc = (const float*)d_in[0];
    const float* fn = (const float*)d_in[1];
    const float* pe = (const float*)d_in[2];
    const float* pt = (const float*)d_in[3];
    const float* nt = (const float*)d_in[4];
    const float* qt = (const float*)d_in[5];
    const float* W1 = (const float*)d_in[6];
    const float* W2 = (const float*)d_in[7];
    const float* W3 = (const float*)d_in[8];
    float* out = (float*)d_out;

    const int n = in_sizes[0] / 3;

    encode_kernel<<<(n + 255) / 256, 256>>>(fc, fn, pe, pt, nt, qt, n);

    cudaFuncSetAttribute(mlp_kernel,
                         cudaFuncAttributeMaxDynamicSharedMemorySize,
                         MLP_SMEM_BYTES);
    mlp_kernel<<<(n + 511) / 512, 256, MLP_SMEM_BYTES>>>(W1, W2, W3, out, n);
}

// round 15
// speedup vs baseline: 1.1347x; 1.1347x over previous
#include <cuda_runtime.h>
#include <cstdint>

#define HG_L 16
#define HG_T (1u << 19)
#define HG_TMASK (HG_T - 1u)
#define WIDTH 64

#define P1 2654435761u
#define P2 805459861u
#define P3 3674653429u

typedef unsigned long long u64;

// Feature scratch: 48 level-slices x 2^20 points, one packed f32x2 each.
#define NPAD_LOG2 20
__device__ u64 g_enc[48u << NPAD_LOG2];   // 402 MB static scratch

// floor(16 * 1.5^l) for l = 0..15
__constant__ float c_res[HG_L] = {
    16.f, 24.f, 36.f, 54.f, 81.f, 121.f, 182.f, 273.f,
    410.f, 615.f, 922.f, 1383.f, 2075.f, 3113.f, 4670.f, 7006.f
};

// ---------- packed f32x2 helpers (Blackwell FFMA2) ----------
__device__ __forceinline__ u64 ffma2(u64 a, u64 b, u64 c) {
    u64 d;
    asm("fma.rn.f32x2 %0, %1, %2, %3;" : "=l"(d) : "l"(a), "l"(b), "l"(c));
    return d;
}
__device__ __forceinline__ u64 dup2(float x) {
    u64 d;
    asm("mov.b64 %0, {%1, %1};" : "=l"(d) : "f"(x));
    return d;
}
__device__ __forceinline__ u64 pack2(float lo, float hi) {
    u64 d;
    asm("mov.b64 %0, {%1, %2};" : "=l"(d) : "f"(lo), "f"(hi));
    return d;
}
__device__ __forceinline__ void unpack2(u64 x, float& lo, float& hi) {
    asm("mov.b64 {%0, %1}, %2;" : "=f"(lo), "=f"(hi) : "l"(x));
}
__device__ __forceinline__ u64 relu2(u64 x) {
    float lo, hi;
    unpack2(x, lo, hi);
    return pack2(fmaxf(lo, 0.f), fmaxf(hi, 0.f));
}

// ---------- gather primitives (R3 scheme, measured best) ----------
__device__ __forceinline__ void gather_pair(const float2* __restrict__ base,
                                            bool even, uint32_t ax0, uint32_t e,
                                            float vx0, float vx1, float wt,
                                            float& f0, float& f1) {
    if (even) {
        uint32_t id0 = (ax0 ^ e) & HG_TMASK;
        float4 q = __ldg((const float4*)base + (id0 >> 1));
        bool h = (id0 & 1u) != 0u;
        float wl = h ? vx1 : vx0;
        float wh = h ? vx0 : vx1;
        f0 = fmaf(wt, fmaf(wl, q.x, wh * q.z), f0);
        f1 = fmaf(wt, fmaf(wl, q.y, wh * q.w), f1);
    } else {
        float2 u = __ldg(base + ((ax0 ^ e) & HG_TMASK));
        float2 v = __ldg(base + (((ax0 + 1u) ^ e) & HG_TMASK));
        f0 = fmaf(wt, fmaf(vx0, u.x, vx1 * v.x), f0);
        f1 = fmaf(wt, fmaf(vx0, u.y, vx1 * v.y), f1);
    }
}

__device__ __forceinline__ void level3(float x0, float x1, float x2, float r,
                                       const float2* __restrict__ base,
                                       float& f0, float& f1) {
    float px = x0 * r, py = x1 * r, pz = x2 * r;
    float fx = floorf(px), fy = floorf(py), fz = floorf(pz);
    float wx = px - fx, wy = py - fy, wz = pz - fz;

    uint32_t ax0 = (uint32_t)fx;
    uint32_t ey0 = (uint32_t)fy * P1, ey1 = ey0 + P1;
    uint32_t ez0 = (uint32_t)fz * P2, ez1 = ez0 + P2;
    float vx0 = 1.f - wx, vx1 = wx;
    float vy0 = 1.f - wy, vy1 = wy;
    float vz0 = 1.f - wz, vz1 = wz;
    const bool even = (ax0 & 1u) == 0u;

    f0 = 0.f; f1 = 0.f;
    gather_pair(base, even, ax0, ey0 ^ ez0, vx0, vx1, vy0 * vz0, f0, f1);
    gather_pair(base, even, ax0, ey0 ^ ez1, vx0, vx1, vy0 * vz1, f0, f1);
    gather_pair(base, even, ax0, ey1 ^ ez0, vx0, vx1, vy1 * vz0, f0, f1);
    gather_pair(base, even, ax0, ey1 ^ ez1, vx0, vx1, vy1 * vz1, f0, f1);
}

__device__ __forceinline__ void level4(float x0, float x1, float x2, float x3,
                                       float r, const float2* __restrict__ base,
                                       float& f0, float& f1) {
    float px = x0 * r, py = x1 * r, pz = x2 * r, pw = x3 * r;
    float fx = floorf(px), fy = floorf(py), fz = floorf(pz), fw = floorf(pw);
    float wx = px - fx, wy = py - fy, wz = pz - fz, ww = pw - fw;

    uint32_t ax0 = (uint32_t)fx;
    uint32_t ey[2], ez[2], ew[2];
    ey[0] = (uint32_t)fy * P1;  ey[1] = ey[0] + P1;
    ez[0] = (uint32_t)fz * P2;  ez[1] = ez[0] + P2;
    ew[0] = (uint32_t)fw * P3;  ew[1] = ew[0] + P3;
    float vx0 = 1.f - wx, vx1 = wx;
    float vy[2] = {1.f - wy, wy};
    float vz[2] = {1.f - wz, wz};
    float vw[2] = {1.f - ww, ww};
    const bool even = (ax0 & 1u) == 0u;

    f0 = 0.f; f1 = 0.f;
#pragma unroll
    for (int c = 0; c < 8; c++) {
        const int by = (c >> 2) & 1, bz = (c >> 1) & 1, bw = c & 1;
        gather_pair(base, even, ax0, ey[by] ^ ez[bz] ^ ew[bw],
                    vx0, vx1, vy[by] * (vz[bz] * vw[bw]), f0, f1);
    }
}

// ---------- kernel 1: encode only (R9 form, measured best) ----------
__global__ __launch_bounds__(256)
void encode_kernel(const float* __restrict__ fc,
                   const float* __restrict__ fn,
                   const float* __restrict__ pe,
                   const float* __restrict__ pos_tab,
                   const float* __restrict__ nrm_tab,
                   const float* __restrict__ pose_tab,
                   int n) {
    const int idx = blockIdx.x * 256 + threadIdx.x;
    if (idx >= n) return;

    {
        float x0 = __ldg(fc + (size_t)idx * 3 + 0);
        float x1 = __ldg(fc + (size_t)idx * 3 + 1);
        float x2 = __ldg(fc + (size_t)idx * 3 + 2);
#pragma unroll 1
        for (int l = 0; l < HG_L; l++) {
            const float2* base = (const float2*)pos_tab + (size_t)l * HG_T;
            float f0, f1;
            level3(x0, x1, x2, c_res[l], base, f0, f1);
            g_enc[((size_t)l << NPAD_LOG2) + idx] = pack2(f0, f1);
        }
    }
    {
        float x0 = __ldg(fn + (size_t)idx * 3 + 0);
        float x1 = __ldg(fn + (size_t)idx * 3 + 1);
        float x2 = __ldg(fn + (size_t)idx * 3 + 2);
#pragma unroll 1
        for (int l = 0; l < HG_L; l++) {
            const float2* base = (const float2*)nrm_tab + (size_t)l * HG_T;
            float f0, f1;
            level3(x0, x1, x2, c_res[l], base, f0, f1);
            g_enc[((size_t)(16 + l) << NPAD_LOG2) + idx] = pack2(f0, f1);
        }
    }
    {
        float x0 = __ldg(pe + (size_t)idx * 4 + 0);
        float x1 = __ldg(pe + (size_t)idx * 4 + 1);
        float x2 = __ldg(pe + (size_t)idx * 4 + 2);
        float x3 = __ldg(pe + (size_t)idx * 4 + 3);
#pragma unroll 1
        for (int l = 0; l < HG_L; l++) {
            const float2* base = (const float2*)pose_tab + (size_t)l * HG_T;
            float f0, f1;
            level4(x0, x1, x2, x3, c_res[l], base, f0, f1);
            g_enc[((size_t)(32 + l) << NPAD_LOG2) + idx] = pack2(f0, f1);
        }
    }
}

// ---------- kernel 2: MLP dual-point, 128-thread CTAs, 2 CTAs/SM ----------
__device__ __forceinline__ void acc_l1_dual(const float* __restrict__ W1s, int row,
                                            float a0, float a1, float b0, float b1,
                                            u64* __restrict__ hpA, u64* __restrict__ hpB) {
    u64 A0 = dup2(a0), A1 = dup2(a1), B0 = dup2(b0), B1 = dup2(b1);
    const ulonglong2* w0 = (const ulonglong2*)(W1s + row * WIDTH);
    const ulonglong2* w1 = (const ulonglong2*)(W1s + (row + 1) * WIDTH);
#pragma unroll
    for (int j = 0; j < 16; j++) {
        ulonglong2 a = w0[j];
        ulonglong2 b = w1[j];
        hpA[2 * j + 0] = ffma2(A0, a.x, ffma2(A1, b.x, hpA[2 * j + 0]));
        hpA[2 * j + 1] = ffma2(A0, a.y, ffma2(A1, b.y, hpA[2 * j + 1]));
        hpB[2 * j + 0] = ffma2(B0, a.x, ffma2(B1, b.x, hpB[2 * j + 0]));
        hpB[2 * j + 1] = ffma2(B0, a.y, ffma2(B1, b.y, hpB[2 * j + 1]));
    }
}

__global__ __launch_bounds__(128, 2)
void mlp_kernel(const float* __restrict__ W1,
                const float* __restrict__ W2,
                const float* __restrict__ W3,
                float* __restrict__ out, int n) {
    __shared__ float W1s[96 * WIDTH];       // 24 KB
    __shared__ float W2Ts[WIDTH * WIDTH];   // 16 KB (transposed)
    __shared__ float W3s[WIDTH * 9];        // 2.25 KB

    const int tid = threadIdx.x;
    for (int i = tid; i < 96 * WIDTH; i += 128) W1s[i] = W1[i];
    for (int i = tid; i < WIDTH * WIDTH; i += 128) {
        int k = i >> 6, j = i & 63;
        W2Ts[j * WIDTH + k] = W2[i];
    }
    for (int i = tid; i < WIDTH * 9; i += 128) W3s[i] = W3[i];
    __syncthreads();

    const int pA = blockIdx.x * 256 + tid;
    const int pB = pA + 128;
    if (pA >= n) return;
    const bool hasB = (pB < n);
    const int cB = hasB ? pB : pA;

    u64 hpA[32], hpB[32];
#pragma unroll
    for (int j = 0; j < 32; j++) { hpA[j] = 0ull; hpB[j] = 0ull; }

    // layer 1: stream features from scratch, weights read once per level
#pragma unroll 1
    for (int l = 0; l < 48; l++) {
        u64 eA = g_enc[((size_t)l << NPAD_LOG2) + pA];
        u64 eB = g_enc[((size_t)l << NPAD_LOG2) + cB];
        float a0, a1, b0, b1;
        unpack2(eA, a0, a1);
        unpack2(eB, b0, b1);
        acc_l1_dual(W1s, 2 * l, a0, a1, b0, b1, hpA, hpB);
    }

    // relu
#pragma unroll
    for (int j = 0; j < 32; j++) { hpA[j] = relu2(hpA[j]); hpB[j] = relu2(hpB[j]); }

    // layers 2 + 3 dual, weights shared (LDS.128 via ulonglong2)
    float accA[9], accB[9];
#pragma unroll
    for (int o = 0; o < 9; o++) { accA[o] = 0.f; accB[o] = 0.f; }

#pragma unroll 1
    for (int j = 0; j < WIDTH; j++) {
        const ulonglong2* wr = (const ulonglong2*)(W2Ts + j * WIDTH);  // 16 x 16B
        u64 sA0 = 0ull, sA1 = 0ull, sB0 = 0ull, sB1 = 0ull;
#pragma unroll
        for (int k = 0; k < 16; k++) {
            ulonglong2 w = wr[k];
            sA0 = ffma2(hpA[2 * k + 0], w.x, sA0);
            sA1 = ffma2(hpA[2 * k + 1], w.y, sA1);
            sB0 = ffma2(hpB[2 * k + 0], w.x, sB0);
            sB1 = ffma2(hpB[2 * k + 1], w.y, sB1);
        }
        float a0, a1, a2, a3, b0, b1, b2, b3;
        unpack2(sA0, a0, a1); unpack2(sA1, a2, a3);
        unpack2(sB0, b0, b1); unpack2(sB1, b2, b3);
        float sA = fmaxf((a0 + a1) + (a2 + a3), 0.f);
        float sB = fmaxf((b0 + b1) + (b2 + b3), 0.f);
        const float* w3 = W3s + j * 9;
#pragma unroll
        for (int o = 0; o < 9; o++) {
            float w = w3[o];
            accA[o] = fmaf(sA, w, accA[o]);
            accB[o] = fmaf(sB, w, accB[o]);
        }
    }

    {
        float* op = out + (size_t)pA * 9;
#pragma unroll
        for (int o = 0; o < 9; o++) op[o] = accA[o];
    }
    if (hasB) {
        float* op = out + (size_t)pB * 9;
#pragma unroll
        for (int o = 0; o < 9; o++) op[o] = accB[o];
    }
}

extern "C" void kernel_launch(void* const* d_in, const int* in_sizes, int n_in,
                              void* d_out, int out_size) {
    const float* fc = (const float*)d_in[0];
    const float* fn = (const float*)d_in[1];
    const float* pe = (const float*)d_in[2];
    const float* pt = (const float*)d_in[3];
    const float* nt = (const float*)d_in[4];
    const float* qt = (const float*)d_in[5];
    const float* W1 = (const float*)d_in[6];
    const float* W2 = (const float*)d_in[7];
    const float* W3 = (const float*)d_in[8];
    float* out = (float*)d_out;

    const int n = in_sizes[0] / 3;

    encode_kernel<<<(n + 255) / 256, 256>>>(fc, fn, pe, pt, nt, qt, n);
    mlp_kernel<<<(n + 255) / 256, 128>>>(W1, W2, W3, out, n);
}

// round 16
// speedup vs baseline: 1.1804x; 1.0403x over previous
#include <cuda_runtime.h>
#include <cstdint>

#define HG_L 16
#define HG_T (1u << 19)
#define HG_TMASK (HG_T - 1u)
#define WIDTH 64

#define P1 2654435761u
#define P2 805459861u
#define P3 3674653429u

typedef unsigned long long u64;

// Feature scratch, pair-packed: 24 pair-slices x 2^20 points x 16 B.
// Pair p holds levels (2p, 2p+1); element = ulonglong2 {level 2p, level 2p+1}.
#define NPAD_LOG2 20
__device__ u64 g_enc[48u << NPAD_LOG2];   // 402 MB static scratch

// floor(16 * 1.5^l) for l = 0..15
__constant__ float c_res[HG_L] = {
    16.f, 24.f, 36.f, 54.f, 81.f, 121.f, 182.f, 273.f,
    410.f, 615.f, 922.f, 1383.f, 2075.f, 3113.f, 4670.f, 7006.f
};

// ---------- packed f32x2 helpers (Blackwell FFMA2) ----------
__device__ __forceinline__ u64 ffma2(u64 a, u64 b, u64 c) {
    u64 d;
    asm("fma.rn.f32x2 %0, %1, %2, %3;" : "=l"(d) : "l"(a), "l"(b), "l"(c));
    return d;
}
__device__ __forceinline__ u64 dup2(float x) {
    u64 d;
    asm("mov.b64 %0, {%1, %1};" : "=l"(d) : "f"(x));
    return d;
}
__device__ __forceinline__ u64 pack2(float lo, float hi) {
    u64 d;
    asm("mov.b64 %0, {%1, %2};" : "=l"(d) : "f"(lo), "f"(hi));
    return d;
}
__device__ __forceinline__ void unpack2(u64 x, float& lo, float& hi) {
    asm("mov.b64 {%0, %1}, %2;" : "=f"(lo), "=f"(hi) : "l"(x));
}
__device__ __forceinline__ u64 relu2(u64 x) {
    float lo, hi;
    unpack2(x, lo, hi);
    return pack2(fmaxf(lo, 0.f), fmaxf(hi, 0.f));
}

// ---------- gather primitives (R3 scheme, measured best) ----------
__device__ __forceinline__ void gather_pair(const float2* __restrict__ base,
                                            bool even, uint32_t ax0, uint32_t e,
                                            float vx0, float vx1, float wt,
                                            float& f0, float& f1) {
    if (even) {
        uint32_t id0 = (ax0 ^ e) & HG_TMASK;
        float4 q = __ldg((const float4*)base + (id0 >> 1));
        bool h = (id0 & 1u) != 0u;
        float wl = h ? vx1 : vx0;
        float wh = h ? vx0 : vx1;
        f0 = fmaf(wt, fmaf(wl, q.x, wh * q.z), f0);
        f1 = fmaf(wt, fmaf(wl, q.y, wh * q.w), f1);
    } else {
        float2 u = __ldg(base + ((ax0 ^ e) & HG_TMASK));
        float2 v = __ldg(base + (((ax0 + 1u) ^ e) & HG_TMASK));
        f0 = fmaf(wt, fmaf(vx0, u.x, vx1 * v.x), f0);
        f1 = fmaf(wt, fmaf(vx0, u.y, vx1 * v.y), f1);
    }
}

__device__ __forceinline__ void level3(float x0, float x1, float x2, float r,
                                       const float2* __restrict__ base,
                                       float& f0, float& f1) {
    float px = x0 * r, py = x1 * r, pz = x2 * r;
    float fx = floorf(px), fy = floorf(py), fz = floorf(pz);
    float wx = px - fx, wy = py - fy, wz = pz - fz;

    uint32_t ax0 = (uint32_t)fx;
    uint32_t ey0 = (uint32_t)fy * P1, ey1 = ey0 + P1;
    uint32_t ez0 = (uint32_t)fz * P2, ez1 = ez0 + P2;
    float vx0 = 1.f - wx, vx1 = wx;
    float vy0 = 1.f - wy, vy1 = wy;
    float vz0 = 1.f - wz, vz1 = wz;
    const bool even = (ax0 & 1u) == 0u;

    f0 = 0.f; f1 = 0.f;
    gather_pair(base, even, ax0, ey0 ^ ez0, vx0, vx1, vy0 * vz0, f0, f1);
    gather_pair(base, even, ax0, ey0 ^ ez1, vx0, vx1, vy0 * vz1, f0, f1);
    gather_pair(base, even, ax0, ey1 ^ ez0, vx0, vx1, vy1 * vz0, f0, f1);
    gather_pair(base, even, ax0, ey1 ^ ez1, vx0, vx1, vy1 * vz1, f0, f1);
}

__device__ __forceinline__ void level4(float x0, float x1, float x2, float x3,
                                       float r, const float2* __restrict__ base,
                                       float& f0, float& f1) {
    float px = x0 * r, py = x1 * r, pz = x2 * r, pw = x3 * r;
    float fx = floorf(px), fy = floorf(py), fz = floorf(pz), fw = floorf(pw);
    float wx = px - fx, wy = py - fy, wz = pz - fz, ww = pw - fw;

    uint32_t ax0 = (uint32_t)fx;
    uint32_t ey[2], ez[2], ew[2];
    ey[0] = (uint32_t)fy * P1;  ey[1] = ey[0] + P1;
    ez[0] = (uint32_t)fz * P2;  ez[1] = ez[0] + P2;
    ew[0] = (uint32_t)fw * P3;  ew[1] = ew[0] + P3;
    float vx0 = 1.f - wx, vx1 = wx;
    float vy[2] = {1.f - wy, wy};
    float vz[2] = {1.f - wz, wz};
    float vw[2] = {1.f - ww, ww};
    const bool even = (ax0 & 1u) == 0u;

    f0 = 0.f; f1 = 0.f;
#pragma unroll
    for (int c = 0; c < 8; c++) {
        const int by = (c >> 2) & 1, bz = (c >> 1) & 1, bw = c & 1;
        gather_pair(base, even, ax0, ey[by] ^ ez[bz] ^ ew[bw],
                    vx0, vx1, vy[by] * (vz[bz] * vw[bw]), f0, f1);
    }
}

// ---------- kernel 1: encode; sequential levels, paired STG.128 ----------
__global__ __launch_bounds__(256)
void encode_kernel(const float* __restrict__ fc,
                   const float* __restrict__ fn,
                   const float* __restrict__ pe,
                   const float* __restrict__ pos_tab,
                   const float* __restrict__ nrm_tab,
                   const float* __restrict__ pose_tab,
                   int n) {
    const int idx = blockIdx.x * 256 + threadIdx.x;
    if (idx >= n) return;
    ulonglong2* enc2 = (ulonglong2*)g_enc;

    {
        float x0 = __ldg(fc + (size_t)idx * 3 + 0);
        float x1 = __ldg(fc + (size_t)idx * 3 + 1);
        float x2 = __ldg(fc + (size_t)idx * 3 + 2);
#pragma unroll 1
        for (int p = 0; p < 8; p++) {
            const int l = 2 * p;
            float f0, f1, g0, g1;
            level3(x0, x1, x2, c_res[l],
                   (const float2*)pos_tab + (size_t)l * HG_T, f0, f1);
            level3(x0, x1, x2, c_res[l + 1],
                   (const float2*)pos_tab + (size_t)(l + 1) * HG_T, g0, g1);
            ulonglong2 v;
            v.x = pack2(f0, f1);
            v.y = pack2(g0, g1);
            enc2[((size_t)p << NPAD_LOG2) + idx] = v;
        }
    }
    {
        float x0 = __ldg(fn + (size_t)idx * 3 + 0);
        float x1 = __ldg(fn + (size_t)idx * 3 + 1);
        float x2 = __ldg(fn + (size_t)idx * 3 + 2);
#pragma unroll 1
        for (int p = 0; p < 8; p++) {
            const int l = 2 * p;
            float f0, f1, g0, g1;
            level3(x0, x1, x2, c_res[l],
                   (const float2*)nrm_tab + (size_t)l * HG_T, f0, f1);
            level3(x0, x1, x2, c_res[l + 1],
                   (const float2*)nrm_tab + (size_t)(l + 1) * HG_T, g0, g1);
            ulonglong2 v;
            v.x = pack2(f0, f1);
            v.y = pack2(g0, g1);
            enc2[((size_t)(8 + p) << NPAD_LOG2) + idx] = v;
        }
    }
    {
        float x0 = __ldg(pe + (size_t)idx * 4 + 0);
        float x1 = __ldg(pe + (size_t)idx * 4 + 1);
        float x2 = __ldg(pe + (size_t)idx * 4 + 2);
        float x3 = __ldg(pe + (size_t)idx * 4 + 3);
#pragma unroll 1
        for (int p = 0; p < 8; p++) {
            const int l = 2 * p;
            float f0, f1, g0, g1;
            level4(x0, x1, x2, x3, c_res[l],
                   (const float2*)pose_tab + (size_t)l * HG_T, f0, f1);
            level4(x0, x1, x2, x3, c_res[l + 1],
                   (const float2*)pose_tab + (size_t)(l + 1) * HG_T, g0, g1);
            ulonglong2 v;
            v.x = pack2(f0, f1);
            v.y = pack2(g0, g1);
            enc2[((size_t)(16 + p) << NPAD_LOG2) + idx] = v;
        }
    }
}

// ---------- kernel 2: MLP dual-point, 128-thread CTAs (R15, best) ----------
__device__ __forceinline__ void acc_l1_dual(const float* __restrict__ W1s, int row,
                                            float a0, float a1, float b0, float b1,
                                            u64* __restrict__ hpA, u64* __restrict__ hpB) {
    u64 A0 = dup2(a0), A1 = dup2(a1), B0 = dup2(b0), B1 = dup2(b1);
    const ulonglong2* w0 = (const ulonglong2*)(W1s + row * WIDTH);
    const ulonglong2* w1 = (const ulonglong2*)(W1s + (row + 1) * WIDTH);
#pragma unroll
    for (int j = 0; j < 16; j++) {
        ulonglong2 a = w0[j];
        ulonglong2 b = w1[j];
        hpA[2 * j + 0] = ffma2(A0, a.x, ffma2(A1, b.x, hpA[2 * j + 0]));
        hpA[2 * j + 1] = ffma2(A0, a.y, ffma2(A1, b.y, hpA[2 * j + 1]));
        hpB[2 * j + 0] = ffma2(B0, a.x, ffma2(B1, b.x, hpB[2 * j + 0]));
        hpB[2 * j + 1] = ffma2(B0, a.y, ffma2(B1, b.y, hpB[2 * j + 1]));
    }
}

__global__ __launch_bounds__(128, 2)
void mlp_kernel(const float* __restrict__ W1,
                const float* __restrict__ W2,
                const float* __restrict__ W3,
                float* __restrict__ out, int n) {
    __shared__ float W1s[96 * WIDTH];       // 24 KB
    __shared__ float W2Ts[WIDTH * WIDTH];   // 16 KB (transposed)
    __shared__ float W3s[WIDTH * 9];        // 2.25 KB

    const int tid = threadIdx.x;
    for (int i = tid; i < 96 * WIDTH; i += 128) W1s[i] = W1[i];
    for (int i = tid; i < WIDTH * WIDTH; i += 128) {
        int k = i >> 6, j = i & 63;
        W2Ts[j * WIDTH + k] = W2[i];
    }
    for (int i = tid; i < WIDTH * 9; i += 128) W3s[i] = W3[i];
    __syncthreads();

    const int pA = blockIdx.x * 256 + tid;
    const int pB = pA + 128;
    if (pA >= n) return;
    const bool hasB = (pB < n);
    const int cB = hasB ? pB : pA;
    const ulonglong2* enc2 = (const ulonglong2*)g_enc;

    u64 hpA[32], hpB[32];
#pragma unroll
    for (int j = 0; j < 32; j++) { hpA[j] = 0ull; hpB[j] = 0ull; }

    // layer 1: paired LDG.128 feature loads (2 levels each), weights shared
#pragma unroll 1
    for (int p = 0; p < 24; p++) {
        ulonglong2 eA = enc2[((size_t)p << NPAD_LOG2) + pA];
        ulonglong2 eB = enc2[((size_t)p << NPAD_LOG2) + cB];
        float a0, a1, b0, b1;
        unpack2(eA.x, a0, a1);
        unpack2(eB.x, b0, b1);
        acc_l1_dual(W1s, 4 * p, a0, a1, b0, b1, hpA, hpB);
        unpack2(eA.y, a0, a1);
        unpack2(eB.y, b0, b1);
        acc_l1_dual(W1s, 4 * p + 2, a0, a1, b0, b1, hpA, hpB);
    }

    // relu
#pragma unroll
    for (int j = 0; j < 32; j++) { hpA[j] = relu2(hpA[j]); hpB[j] = relu2(hpB[j]); }

    // layers 2 + 3 dual, weights shared (LDS.128 via ulonglong2)
    float accA[9], accB[9];
#pragma unroll
    for (int o = 0; o < 9; o++) { accA[o] = 0.f; accB[o] = 0.f; }

#pragma unroll 1
    for (int j = 0; j < WIDTH; j++) {
        const ulonglong2* wr = (const ulonglong2*)(W2Ts + j * WIDTH);  // 16 x 16B
        u64 sA0 = 0ull, sA1 = 0ull, sB0 = 0ull, sB1 = 0ull;
#pragma unroll
        for (int k = 0; k < 16; k++) {
            ulonglong2 w = wr[k];
            sA0 = ffma2(hpA[2 * k + 0], w.x, sA0);
            sA1 = ffma2(hpA[2 * k + 1], w.y, sA1);
            sB0 = ffma2(hpB[2 * k + 0], w.x, sB0);
            sB1 = ffma2(hpB[2 * k + 1], w.y, sB1);
        }
        float a0, a1, a2, a3, b0, b1, b2, b3;
        unpack2(sA0, a0, a1); unpack2(sA1, a2, a3);
        unpack2(sB0, b0, b1); unpack2(sB1, b2, b3);
        float sA = fmaxf((a0 + a1) + (a2 + a3), 0.f);
        float sB = fmaxf((b0 + b1) + (b2 + b3), 0.f);
        const float* w3 = W3s + j * 9;
#pragma unroll
        for (int o = 0; o < 9; o++) {
            float w = w3[o];
            accA[o] = fmaf(sA, w, accA[o]);
            accB[o] = fmaf(sB, w, accB[o]);
        }
    }

    {
        float* op = out + (size_t)pA * 9;
#pragma unroll
        for (int o = 0; o < 9; o++) op[o] = accA[o];
    }
    if (hasB) {
        float* op = out + (size_t)pB * 9;
#pragma unroll
        for (int o = 0; o < 9; o++) op[o] = accB[o];
    }
}

extern "C" void kernel_launch(void* const* d_in, const int* in_sizes, int n_in,
                              void* d_out, int out_size) {
    const float* fc = (const float*)d_in[0];
    const float* fn = (const float*)d_in[1];
    const float* pe = (const float*)d_in[2];
    const float* pt = (const float*)d_in[3];
    const float* nt = (const float*)d_in[4];
    const float* qt = (const float*)d_in[5];
    const float* W1 = (const float*)d_in[6];
    const float* W2 = (const float*)d_in[7];
    const float* W3 = (const float*)d_in[8];
    float* out = (float*)d_out;

    const int n = in_sizes[0] / 3;

    encode_kernel<<<(n + 255) / 256, 256>>>(fc, fn, pe, pt, nt, qt, n);
    mlp_kernel<<<(n + 255) / 256, 128>>>(W1, W2, W3, out, n);
}